// round 13
// baseline (speedup 1.0000x reference)
#include <cuda_runtime.h>
#include <cuda_bf16.h>
#include <cstdint>
#include <math.h>

#define BB 256
#define FF 512
#define CC 100000
#define SSC 64.0f
#define MMAR 0.4f
#define KVP 0.7f

#define BM 128
#define BN 128
#define KC 32
#define NCH (FF / KC)                 // 16
#define NTILES ((CC + BN - 1) / BN)   // 782
#define CEX 64                        // overflow y-blocks carrying k_correct work

#define STRA 40                        // A: bf16 elems/row (80B rows, ldsm conflict-free)
// B staging: 144B-stride rows; fp32 chunk in place, bf16 written in place (sparse groups)

// dynamic smem (bytes): As x3 | Bst x3
#define ASB 10240                      // 128*80
#define BSTB 18432                     // 128*144
#define OFF_AS 0
#define OFF_B (3 * ASB)                // 30720
#define DSMEM (OFF_B + 3 * BSTB)       // 86016

#define KE  92.33248261972343f         // SSC * log2(e)
#define KEM 36.93299304788937f         // KE * MMAR

__device__ float g_emb[BB * FF];
__device__ __nv_bfloat16 g_embh[BB * FF];
__device__ float g_newq[BB * FF];
__device__ float g_oldn[BB * FF];
__device__ float g_rowsum1[BB];
__device__ float g_rowsum2[BB];
__device__ float g_pos1[BB];
__device__ float g_pos2[BB];
__device__ int   g_owner[BB];

static __device__ __forceinline__ uint32_t s2u(const void* p) {
    uint32_t a;
    asm("{ .reg .u64 t; cvta.to.shared.u64 t, %1; cvt.u32.u64 %0, t; }" : "=r"(a) : "l"(p));
    return a;
}

static __device__ __forceinline__ float ex2(float x) {
    float r;
    asm("ex2.approx.f32 %0, %1;" : "=f"(r) : "f"(x));
    return r;
}

#define LDSM4(r0, r1, r2, r3, addr) \
    asm volatile("ldmatrix.sync.aligned.m8n8.x4.shared.b16 {%0,%1,%2,%3}, [%4];" \
                 : "=r"(r0), "=r"(r1), "=r"(r2), "=r"(r3) : "r"(addr))

#define MMA16816(d, a, b) \
    asm volatile("mma.sync.aligned.m16n8k16.row.col.f32.bf16.bf16.f32 " \
                 "{%0,%1,%2,%3},{%4,%5,%6,%7},{%8,%9},{%0,%1,%2,%3};" \
                 : "+f"((d)[0]), "+f"((d)[1]), "+f"((d)[2]), "+f"((d)[3]) \
                 : "r"((a)[0]), "r"((a)[1]), "r"((a)[2]), "r"((a)[3]), \
                   "r"((b)[0]), "r"((b)[1]))

static __device__ __forceinline__ void cp16(uint32_t dst, const void* gsrc) {
    asm volatile("cp.async.cg.shared.global [%0], [%1], 16;"
                 :: "r"(dst), "l"(gsrc) : "memory");
}
#define CP_COMMIT() asm volatile("cp.async.commit_group;" ::: "memory")
#define CP_WAIT0()  asm volatile("cp.async.wait_group 0;" ::: "memory")
#define CP_WAIT1()  asm volatile("cp.async.wait_group 1;" ::: "memory")

static __device__ __forceinline__ uint32_t pk(float x, float y) {
    __nv_bfloat162 h = __floats2bfloat162_rn(x, y);
    return *(uint32_t*)&h;
}

// ---------------------------------------------------------------------------
// K1: normalize input rows (eps 1e-5)
__global__ void k_norm_input(const float* __restrict__ inp) {
    int b = blockIdx.x, t = threadIdx.x;
    __shared__ float red[128];
    float s = 0.f;
    for (int k = t; k < FF; k += 128) { float v = inp[b * FF + k]; s += v * v; }
    red[t] = s; __syncthreads();
    for (int o = 64; o > 0; o >>= 1) { if (t < o) red[t] += red[t + o]; __syncthreads(); }
    float inv = 1.f / fmaxf(sqrtf(red[0]), 1e-5f);
    for (int k = t; k < FF; k += 128) {
        float e = inp[b * FF + k] * inv;
        g_emb[b * FF + k] = e;
        g_embh[b * FF + k] = __float2bfloat16(e);
    }
    if (t == 0) { g_rowsum1[b] = 0.f; g_rowsum2[b] = 0.f; }
}

// ---------------------------------------------------------------------------
// K2: virtual-prototype update for the 256 labeled rows (queue untouched)
__global__ void k_queue_update(const float* __restrict__ queue, const int* __restrict__ label) {
    int b = blockIdx.x, t = threadIdx.x;
    int lb = label[b];
    const float* q = queue + (size_t)lb * FF;
    const float* e = g_emb + b * FF;
    __shared__ float r1[128], r2[128];
    float sq = 0.f, dd = 0.f;
    for (int k = t; k < FF; k += 128) { float qa = q[k], ea = e[k]; sq += qa * qa; dd += qa * ea; }
    r1[t] = sq; r2[t] = dd; __syncthreads();
    for (int o = 64; o > 0; o >>= 1) {
        if (t < o) { r1[t] += r1[t + o]; r2[t] += r2[t + o]; }
        __syncthreads();
    }
    float invold = 1.f / fmaxf(sqrtf(r1[0]), 1e-12f);
    float drift = r2[0];
    float factor = drift / (1.f + fabsf(drift));
    __syncthreads();
    float sn = 0.f;
    for (int k = t; k < FF; k += 128) {
        float v = factor * q[k] + (1.f - factor) * e[k];
        sn += v * v;
    }
    r1[t] = sn; __syncthreads();
    for (int o = 64; o > 0; o >>= 1) { if (t < o) r1[t] += r1[t + o]; __syncthreads(); }
    float invnew = 1.f / fmaxf(sqrtf(r1[0]), 1e-12f);
    for (int k = t; k < FF; k += 128) {
        float v = factor * q[k] + (1.f - factor) * e[k];
        g_newq[b * FF + k] = v * invnew;
        g_oldn[b * FF + k] = q[k] * invold;
    }
    if (t == 0) {
        int own = 1;
        for (int j = b + 1; j < BB; j++) if (label[j] == lb) { own = 0; break; }
        g_owner[b] = own;
    }
}

// ---------------------------------------------------------------------------
// no-op spacer so k_gemm lands in the ncu capture slot (launch #4)
__global__ void k_nop() {}

// ---------------------------------------------------------------------------
// queue-column fixups, executed by overflow blocks of the GEMM grid.
static __device__ void do_correct(int b0, int jbase, const int* __restrict__ label,
                                  uint8_t* sm) {
    float4* es0 = (float4*)sm;
    float4* es1 = es0 + FF / 4;
    float*  wneg = (float*)(es1 + FF / 4);
    int tid = threadIdx.x;
    int w = tid >> 5, lane = tid & 31;
    for (int k = tid; k < FF / 4; k += 256) {
        es0[k] = ((const float4*)(g_emb + (size_t)b0 * FF))[k];
        es1[k] = ((const float4*)(g_emb + (size_t)(b0 + 1) * FF))[k];
    }
    __syncthreads();
    int lab0 = label[b0], lab1 = label[b0 + 1];
    float neg0 = 0.f, neg1 = 0.f;
#pragma unroll 1
    for (int it = 0; it < 4; it++) {
        int j0 = jbase + (w + 8 * it) * 4;
        float doo[2][4] = {}, dnn[2][4] = {};
#pragma unroll
        for (int kit = 0; kit < 4; kit++) {
            int k4 = lane + 32 * kit;
            float4 e0 = es0[k4], e1 = es1[k4];
#pragma unroll
            for (int s = 0; s < 4; s++) {
                float4 o4 = ((const float4*)(g_oldn + (size_t)(j0 + s) * FF))[k4];
                float4 n4 = ((const float4*)(g_newq + (size_t)(j0 + s) * FF))[k4];
                doo[0][s] += e0.x * o4.x + e0.y * o4.y + e0.z * o4.z + e0.w * o4.w;
                dnn[0][s] += e0.x * n4.x + e0.y * n4.y + e0.z * n4.z + e0.w * n4.w;
                doo[1][s] += e1.x * o4.x + e1.y * o4.y + e1.z * o4.z + e1.w * o4.w;
                dnn[1][s] += e1.x * n4.x + e1.y * n4.y + e1.z * n4.z + e1.w * n4.w;
            }
        }
#pragma unroll
        for (int o = 16; o > 0; o >>= 1)
#pragma unroll
            for (int s = 0; s < 4; s++) {
                doo[0][s] += __shfl_xor_sync(0xffffffffu, doo[0][s], o);
                dnn[0][s] += __shfl_xor_sync(0xffffffffu, dnn[0][s], o);
                doo[1][s] += __shfl_xor_sync(0xffffffffu, doo[1][s], o);
                dnn[1][s] += __shfl_xor_sync(0xffffffffu, dnn[1][s], o);
            }
        if (lane < 4) {
            int j = j0 + lane;
            if (g_owner[j]) {
                int lj = label[j];
                neg0 -= __expf(SSC * doo[0][lane]);
                if (lj == lab0) g_pos2[b0] = __expf(-SSC * (1.f - KVP) * dnn[0][lane]);
                else neg0 += __expf(SSC * dnn[0][lane]);
                neg1 -= __expf(SSC * doo[1][lane]);
                if (lj == lab1) g_pos2[b0 + 1] = __expf(-SSC * (1.f - KVP) * dnn[1][lane]);
                else neg1 += __expf(SSC * dnn[1][lane]);
            }
        }
    }
    neg0 += __shfl_xor_sync(0xffffffffu, neg0, 1);
    neg0 += __shfl_xor_sync(0xffffffffu, neg0, 2);
    neg1 += __shfl_xor_sync(0xffffffffu, neg1, 1);
    neg1 += __shfl_xor_sync(0xffffffffu, neg1, 2);
    if (lane == 0) { wneg[0 * 8 + w] = neg0; wneg[1 * 8 + w] = neg1; }
    __syncthreads();
    if (tid < 2) {
        float s = 0.f;
        for (int i = 0; i < 8; i++) s += wneg[tid * 8 + i];
        atomicAdd(&g_rowsum2[b0 + tid], s);
    }
}

// ---------------------------------------------------------------------------
// K3: HMMA GEMM (R11 core: KC=32, 3-stage cp.async, in-place B convert) with a
// branchless MUFU epilogue: per element FFMA + ex2.approx + FADD.
// grid(2, NTILES+CEX, 2): x = m-tile, y = class tile, z = pass.
__global__ void __launch_bounds__(256, 2)
k_gemm(const float* __restrict__ Wt, const float* __restrict__ Qu, const int* __restrict__ label) {
    extern __shared__ uint8_t sm[];
    __shared__ float s_nsq[BN];
    __shared__ float s_ivk[BN];     // KE * invn (0 for OOB)
    __shared__ float s_bias[BN];    // 0, or -1e38 for OOB columns (ex2 -> 0)
    __shared__ float s_row[BM];
    __shared__ int s_lab[BM];

    if (blockIdx.y >= NTILES) {
        int cidx = (int)blockIdx.x + 2 * ((int)blockIdx.y - NTILES);  // 0..127
        do_correct(cidx * 2, (int)blockIdx.z * 128, label, sm);
        return;
    }

    int pass = blockIdx.z;
    const float* W = pass ? Qu : Wt;
    int m0 = blockIdx.x * BM;
    int c0 = blockIdx.y * BN;
    int tid = threadIdx.x;
    int wid = tid >> 5, lane = tid & 31;
    int mw = wid >> 2, nw = wid & 3;     // 2x4 warp grid, 64x32 warp tile
    int rin = lane & 7, seg = lane >> 3;

    if (tid < BM) { s_row[tid] = 0.f; s_lab[tid] = label[m0 + tid]; }

    // --- contiguous warp-level load mapping ---
    int arow0 = 16 * wid + (lane >> 2);        // A: 8 rows x 4 lanes per instr
    int aq    = lane & 3;
    int brow0 = 16 * wid + (lane >> 3);        // B: 4 rows x 8 lanes per instr
    int bq    = lane & 7;
    const uint8_t* aAg = (const uint8_t*)(g_embh + (size_t)(m0 + arow0) * FF) + aq * 16;
    const uint8_t* bAg[4];
#pragma unroll
    for (int i = 0; i < 4; i++) {
        int gr = min(c0 + brow0 + 4 * i, CC - 1);
        bAg[i] = (const uint8_t*)(W + (size_t)gr * FF) + bq * 16;
    }

    uint32_t aAs = s2u(sm + OFF_AS);
    uint32_t aBst = s2u(sm + OFF_B);
    uint32_t aoff0 = (uint32_t)(arow0 * 80 + aq * 16);
    uint32_t boffL[4];
#pragma unroll
    for (int i = 0; i < 4; i++) boffL[i] = (uint32_t)((brow0 + 4 * i) * 144 + bq * 16);

    // convert mapping: thread handles row crow, 64B half ch (its own warp's cp data)
    int crow = tid >> 1, ch = tid & 1;
    uint32_t cvoff = (uint32_t)(crow * 144 + ch * 64);

    float d[4][4][4];
#pragma unroll
    for (int i = 0; i < 4; i++)
#pragma unroll
        for (int j = 0; j < 4; j++)
#pragma unroll
            for (int e = 0; e < 4; e++) d[i][j][e] = 0.f;
    float ssacc = 0.f;

#define ISSUE(k) do { \
        int _s = (k) % 3; \
        uint32_t ad = aAs + _s * ASB + aoff0; \
        const uint8_t* ag = aAg + (size_t)(k) * 64; \
        cp16(ad, ag); \
        cp16(ad + 8 * 80, ag + (size_t)8 * FF * 2); \
        uint32_t bd = aBst + _s * BSTB; \
        cp16(bd + boffL[0], bAg[0] + (size_t)(k) * 128); \
        cp16(bd + boffL[1], bAg[1] + (size_t)(k) * 128); \
        cp16(bd + boffL[2], bAg[2] + (size_t)(k) * 128); \
        cp16(bd + boffL[3], bAg[3] + (size_t)(k) * 128); \
        CP_COMMIT(); \
    } while (0)

    // in-place fp32 -> bf16 (sparse groups): reads its own warp's 64B, writes subsets
#define CONVERT(k) do { \
        uint8_t* bp = sm + OFF_B + ((k) % 3) * BSTB + cvoff; \
        float4 f0 = *(float4*)(bp);      float4 f1 = *(float4*)(bp + 16); \
        float4 f2 = *(float4*)(bp + 32); float4 f3 = *(float4*)(bp + 48); \
        ssacc += f0.x * f0.x + f0.y * f0.y + f0.z * f0.z + f0.w * f0.w \
               + f1.x * f1.x + f1.y * f1.y + f1.z * f1.z + f1.w * f1.w \
               + f2.x * f2.x + f2.y * f2.y + f2.z * f2.z + f2.w * f2.w \
               + f3.x * f3.x + f3.y * f3.y + f3.z * f3.z + f3.w * f3.w; \
        uint4 q0, q1; \
        q0.x = pk(f0.x, f0.y); q0.y = pk(f0.z, f0.w); \
        q0.z = pk(f1.x, f1.y); q0.w = pk(f1.z, f1.w); \
        q1.x = pk(f2.x, f2.y); q1.y = pk(f2.z, f2.w); \
        q1.z = pk(f3.x, f3.y); q1.w = pk(f3.z, f3.w); \
        *(uint4*)(bp) = q0; \
        *(uint4*)(bp + 32) = q1; \
    } while (0)

    ISSUE(0);
    ISSUE(1);
    CP_WAIT1();
    __syncwarp();
    CONVERT(0);

    for (int c = 0; c < NCH; c++) {
        __syncthreads();
        if (c + 2 < NCH) ISSUE(c + 2);
        // ---- MMA on chunk c first (bf16 already in place)
        uint32_t bas = aAs + (c % 3) * ASB;
        uint32_t bbs = aBst + (c % 3) * BSTB;
#pragma unroll
        for (int ks = 0; ks < 2; ks++) {
            int kk = ks * 16;
            uint32_t bfr[4][2];
#pragma unroll
            for (int bh = 0; bh < 2; bh++) {
                int row = nw * 32 + bh * 16 + (seg >> 1) * 8 + rin;
                uint32_t r0, r1, r2, r3;
                LDSM4(r0, r1, r2, r3, bbs + (uint32_t)(row * 144 + kk * 4 + (seg & 1) * 32));
                bfr[bh * 2][0] = r0;     bfr[bh * 2][1] = r1;
                bfr[bh * 2 + 1][0] = r2; bfr[bh * 2 + 1][1] = r3;
            }
#pragma unroll
            for (int mf = 0; mf < 4; mf++) {
                int row = mw * 64 + mf * 16 + (seg & 1) * 8 + rin;
                int col = kk + (seg >> 1) * 8;
                uint32_t af[4];
                LDSM4(af[0], af[1], af[2], af[3], bas + (uint32_t)(row * STRA + col) * 2);
#pragma unroll
                for (int nt = 0; nt < 4; nt++) MMA16816(d[mf][nt], af, bfr[nt]);
            }
        }
        // ---- then wait for chunk c+1 and convert in place
        if (c + 1 < NCH) {
            if (c + 2 < NCH) CP_WAIT1(); else CP_WAIT0();
            __syncwarp();
            CONVERT(c + 1);
        }
    }

    // class norms: threads (2r, 2r+1) covered row r
    ssacc += __shfl_xor_sync(0xffffffffu, ssacc, 1);
    if (ch == 0) s_nsq[crow] = ssacc;
    __syncthreads();
    if (tid < BN) {
        int gc = c0 + tid;
        bool ok = gc < CC;
        float eps = pass ? 1e-12f : 1e-5f;
        s_ivk[tid] = ok ? KE / fmaxf(sqrtf(s_nsq[tid]), eps) : 0.f;
        s_bias[tid] = ok ? 0.f : -1e38f;
    }
    __syncthreads();

    // ---- branchless epilogue: 3 instrs/element + rare label fix (pass 0) ----
    int g4 = lane >> 2, j4 = lane & 3;
    // hoist this thread's 8 column coefficients
    float ivk8[4][2], bias8[4][2];
#pragma unroll
    for (int nt = 0; nt < 4; nt++)
#pragma unroll
        for (int e = 0; e < 2; e++) {
            int lc = nw * 32 + nt * 8 + j4 * 2 + e;
            ivk8[nt][e] = s_ivk[lc];
            bias8[nt][e] = s_bias[lc];
        }
#pragma unroll
    for (int mf = 0; mf < 4; mf++) {
        int ra = mw * 64 + mf * 16 + g4;
        int rb = ra + 8;
        float sa = 0.f, sb = 0.f;
#pragma unroll
        for (int nt = 0; nt < 4; nt++) {
#pragma unroll
            for (int e = 0; e < 2; e++) {
                sa += ex2(fmaf(d[mf][nt][e],     ivk8[nt][e], bias8[nt][e]));
                sb += ex2(fmaf(d[mf][nt][e + 2], ivk8[nt][e], bias8[nt][e]));
            }
        }
        if (pass == 0) {
            // label-column fix (executed only when the label falls in this tile)
            int la = s_lab[ra];
            int lcA = la - c0;
            if ((unsigned)lcA < BN) {
                int rel = lcA - nw * 32;
                if ((unsigned)rel < 32 && (rel >> 1 & 3) == j4) {
                    int nt = rel >> 3, e = rel & 1;
                    float ex = ex2(fmaf(d[mf][nt][e], ivk8[nt][e], bias8[nt][e]));
                    sa -= ex;
                    g_pos1[m0 + ra] = ex2(fmaf(-d[mf][nt][e], ivk8[nt][e], KEM));
                }
            }
            int lb = s_lab[rb];
            int lcB = lb - c0;
            if ((unsigned)lcB < BN) {
                int rel = lcB - nw * 32;
                if ((unsigned)rel < 32 && (rel >> 1 & 3) == j4) {
                    int nt = rel >> 3, e = rel & 1;
                    float ex = ex2(fmaf(d[mf][nt][e + 2], ivk8[nt][e], bias8[nt][e]));
                    sb -= ex;
                    g_pos1[m0 + rb] = ex2(fmaf(-d[mf][nt][e + 2], ivk8[nt][e], KEM));
                }
            }
        }
        sa += __shfl_xor_sync(0xffffffffu, sa, 1);
        sa += __shfl_xor_sync(0xffffffffu, sa, 2);
        sb += __shfl_xor_sync(0xffffffffu, sb, 1);
        sb += __shfl_xor_sync(0xffffffffu, sb, 2);
        if (j4 == 0) { atomicAdd(&s_row[ra], sa); atomicAdd(&s_row[rb], sb); }
    }
    __syncthreads();
    if (tid < BM)
        atomicAdd(pass ? &g_rowsum2[m0 + tid] : &g_rowsum1[m0 + tid], s_row[tid]);
#undef ISSUE
#undef CONVERT
}

// ---------------------------------------------------------------------------
// K6: EPL loss
__global__ void k_final(float* __restrict__ out) {
    int t = threadIdx.x;
    __shared__ float red[256];
    float v = log1pf(g_rowsum1[t] * g_pos1[t]) + log1pf(g_rowsum2[t] * g_pos2[t]);
    red[t] = v; __syncthreads();
    for (int o = 128; o > 0; o >>= 1) { if (t < o) red[t] += red[t + o]; __syncthreads(); }
    if (t == 0) out[0] = red[0] / (2.f * BB);
}

// ---------------------------------------------------------------------------
extern "C" void kernel_launch(void* const* d_in, const int* in_sizes, int n_in,
                              void* d_out, int out_size) {
    const float* inp    = (const float*)d_in[0];
    const float* weight = (const float*)d_in[1];
    const float* queue  = (const float*)d_in[2];
    const int*   label  = (const int*)d_in[3];
    float* out = (float*)d_out;

    cudaFuncSetAttribute(k_gemm, cudaFuncAttributeMaxDynamicSharedMemorySize, DSMEM);

    k_norm_input<<<BB, 128>>>(inp);
    k_queue_update<<<BB, 128>>>(queue, label);
    k_nop<<<1, 32>>>();                   // spacer: puts k_gemm in the ncu slot
    dim3 grid(2, NTILES + CEX, 2);
    k_gemm<<<grid, 256, DSMEM>>>(weight, queue, label);
    k_final<<<1, 256>>>(out);
}

// round 14
// speedup vs baseline: 1.6708x; 1.6708x over previous
#include <cuda_runtime.h>
#include <cuda_bf16.h>
#include <cstdint>
#include <math.h>

#define BB 256
#define FF 512
#define CC 100000
#define SSC 64.0f
#define MMAR 0.4f
#define KVP 0.7f

#define BM 128
#define BN 128
#define KC 32
#define NCH (FF / KC)                 // 16
#define NTILES ((CC + BN - 1) / BN)   // 782
#define CEX 64                        // overflow y-blocks carrying k_correct work

#define STRA 40                        // A: bf16 elems/row (80B rows, ldsm conflict-free)
// B staging: 144B-stride rows; fp32 chunk in place, bf16 written in place (sparse groups)

// dynamic smem (bytes): As x3 | Bst x3
#define ASB 10240                      // 128*80
#define BSTB 18432                     // 128*144
#define OFF_AS 0
#define OFF_B (3 * ASB)                // 30720
#define DSMEM (OFF_B + 3 * BSTB)       // 86016

#define KE  92.33248261972343f         // SSC * log2(e)
#define KEM 36.93299304788937f         // KE * MMAR

__device__ float g_emb[BB * FF];
__device__ __nv_bfloat16 g_embh[BB * FF];
__device__ float g_newq[BB * FF];
__device__ float g_oldn[BB * FF];
__device__ float g_rowsum1[BB];
__device__ float g_rowsum2[BB];
__device__ float g_pos1[BB];
__device__ float g_pos2[BB];
__device__ int   g_owner[BB];

static __device__ __forceinline__ uint32_t s2u(const void* p) {
    uint32_t a;
    asm("{ .reg .u64 t; cvta.to.shared.u64 t, %1; cvt.u32.u64 %0, t; }" : "=r"(a) : "l"(p));
    return a;
}

static __device__ __forceinline__ float ex2(float x) {
    float r;
    asm("ex2.approx.f32 %0, %1;" : "=f"(r) : "f"(x));
    return r;
}

#define LDSM4(r0, r1, r2, r3, addr) \
    asm volatile("ldmatrix.sync.aligned.m8n8.x4.shared.b16 {%0,%1,%2,%3}, [%4];" \
                 : "=r"(r0), "=r"(r1), "=r"(r2), "=r"(r3) : "r"(addr))

#define MMA16816(d, a, b) \
    asm volatile("mma.sync.aligned.m16n8k16.row.col.f32.bf16.bf16.f32 " \
                 "{%0,%1,%2,%3},{%4,%5,%6,%7},{%8,%9},{%0,%1,%2,%3};" \
                 : "+f"((d)[0]), "+f"((d)[1]), "+f"((d)[2]), "+f"((d)[3]) \
                 : "r"((a)[0]), "r"((a)[1]), "r"((a)[2]), "r"((a)[3]), \
                   "r"((b)[0]), "r"((b)[1]))

static __device__ __forceinline__ void cp16(uint32_t dst, const void* gsrc) {
    asm volatile("cp.async.cg.shared.global [%0], [%1], 16;"
                 :: "r"(dst), "l"(gsrc) : "memory");
}
#define CP_COMMIT() asm volatile("cp.async.commit_group;" ::: "memory")
#define CP_WAIT0()  asm volatile("cp.async.wait_group 0;" ::: "memory")
#define CP_WAIT1()  asm volatile("cp.async.wait_group 1;" ::: "memory")

static __device__ __forceinline__ uint32_t pk(float x, float y) {
    __nv_bfloat162 h = __floats2bfloat162_rn(x, y);
    return *(uint32_t*)&h;
}

// ---------------------------------------------------------------------------
// K1: normalize input rows (eps 1e-5)
__global__ void k_norm_input(const float* __restrict__ inp) {
    int b = blockIdx.x, t = threadIdx.x;
    __shared__ float red[128];
    float s = 0.f;
    for (int k = t; k < FF; k += 128) { float v = inp[b * FF + k]; s += v * v; }
    red[t] = s; __syncthreads();
    for (int o = 64; o > 0; o >>= 1) { if (t < o) red[t] += red[t + o]; __syncthreads(); }
    float inv = 1.f / fmaxf(sqrtf(red[0]), 1e-5f);
    for (int k = t; k < FF; k += 128) {
        float e = inp[b * FF + k] * inv;
        g_emb[b * FF + k] = e;
        g_embh[b * FF + k] = __float2bfloat16(e);
    }
    if (t == 0) { g_rowsum1[b] = 0.f; g_rowsum2[b] = 0.f; }
}

// ---------------------------------------------------------------------------
// K2: virtual-prototype update for the 256 labeled rows (queue untouched)
__global__ void k_queue_update(const float* __restrict__ queue, const int* __restrict__ label) {
    int b = blockIdx.x, t = threadIdx.x;
    int lb = label[b];
    const float* q = queue + (size_t)lb * FF;
    const float* e = g_emb + b * FF;
    __shared__ float r1[128], r2[128];
    float sq = 0.f, dd = 0.f;
    for (int k = t; k < FF; k += 128) { float qa = q[k], ea = e[k]; sq += qa * qa; dd += qa * ea; }
    r1[t] = sq; r2[t] = dd; __syncthreads();
    for (int o = 64; o > 0; o >>= 1) {
        if (t < o) { r1[t] += r1[t + o]; r2[t] += r2[t + o]; }
        __syncthreads();
    }
    float invold = 1.f / fmaxf(sqrtf(r1[0]), 1e-12f);
    float drift = r2[0];
    float factor = drift / (1.f + fabsf(drift));
    __syncthreads();
    float sn = 0.f;
    for (int k = t; k < FF; k += 128) {
        float v = factor * q[k] + (1.f - factor) * e[k];
        sn += v * v;
    }
    r1[t] = sn; __syncthreads();
    for (int o = 64; o > 0; o >>= 1) { if (t < o) r1[t] += r1[t + o]; __syncthreads(); }
    float invnew = 1.f / fmaxf(sqrtf(r1[0]), 1e-12f);
    for (int k = t; k < FF; k += 128) {
        float v = factor * q[k] + (1.f - factor) * e[k];
        g_newq[b * FF + k] = v * invnew;
        g_oldn[b * FF + k] = q[k] * invold;
    }
    if (t == 0) {
        int own = 1;
        for (int j = b + 1; j < BB; j++) if (label[j] == lb) { own = 0; break; }
        g_owner[b] = own;
    }
}

// ---------------------------------------------------------------------------
// no-op spacer so k_gemm lands in the ncu capture slot (launch #4)
__global__ void k_nop() {}

// ---------------------------------------------------------------------------
// queue-column fixups, executed by overflow blocks of the GEMM grid.
static __device__ void do_correct(int b0, int jbase, const int* __restrict__ label,
                                  uint8_t* sm) {
    float4* es0 = (float4*)sm;
    float4* es1 = es0 + FF / 4;
    float*  wneg = (float*)(es1 + FF / 4);
    int tid = threadIdx.x;
    int w = tid >> 5, lane = tid & 31;
    for (int k = tid; k < FF / 4; k += 256) {
        es0[k] = ((const float4*)(g_emb + (size_t)b0 * FF))[k];
        es1[k] = ((const float4*)(g_emb + (size_t)(b0 + 1) * FF))[k];
    }
    __syncthreads();
    int lab0 = label[b0], lab1 = label[b0 + 1];
    float neg0 = 0.f, neg1 = 0.f;
#pragma unroll 1
    for (int it = 0; it < 4; it++) {
        int j0 = jbase + (w + 8 * it) * 4;
        float doo[2][4] = {}, dnn[2][4] = {};
#pragma unroll
        for (int kit = 0; kit < 4; kit++) {
            int k4 = lane + 32 * kit;
            float4 e0 = es0[k4], e1 = es1[k4];
#pragma unroll
            for (int s = 0; s < 4; s++) {
                float4 o4 = ((const float4*)(g_oldn + (size_t)(j0 + s) * FF))[k4];
                float4 n4 = ((const float4*)(g_newq + (size_t)(j0 + s) * FF))[k4];
                doo[0][s] += e0.x * o4.x + e0.y * o4.y + e0.z * o4.z + e0.w * o4.w;
                dnn[0][s] += e0.x * n4.x + e0.y * n4.y + e0.z * n4.z + e0.w * n4.w;
                doo[1][s] += e1.x * o4.x + e1.y * o4.y + e1.z * o4.z + e1.w * o4.w;
                dnn[1][s] += e1.x * n4.x + e1.y * n4.y + e1.z * n4.z + e1.w * n4.w;
            }
        }
#pragma unroll
        for (int o = 16; o > 0; o >>= 1)
#pragma unroll
            for (int s = 0; s < 4; s++) {
                doo[0][s] += __shfl_xor_sync(0xffffffffu, doo[0][s], o);
                dnn[0][s] += __shfl_xor_sync(0xffffffffu, dnn[0][s], o);
                doo[1][s] += __shfl_xor_sync(0xffffffffu, doo[1][s], o);
                dnn[1][s] += __shfl_xor_sync(0xffffffffu, dnn[1][s], o);
            }
        if (lane < 4) {
            int j = j0 + lane;
            if (g_owner[j]) {
                int lj = label[j];
                neg0 -= __expf(SSC * doo[0][lane]);
                if (lj == lab0) g_pos2[b0] = __expf(-SSC * (1.f - KVP) * dnn[0][lane]);
                else neg0 += __expf(SSC * dnn[0][lane]);
                neg1 -= __expf(SSC * doo[1][lane]);
                if (lj == lab1) g_pos2[b0 + 1] = __expf(-SSC * (1.f - KVP) * dnn[1][lane]);
                else neg1 += __expf(SSC * dnn[1][lane]);
            }
        }
    }
    neg0 += __shfl_xor_sync(0xffffffffu, neg0, 1);
    neg0 += __shfl_xor_sync(0xffffffffu, neg0, 2);
    neg1 += __shfl_xor_sync(0xffffffffu, neg1, 1);
    neg1 += __shfl_xor_sync(0xffffffffu, neg1, 2);
    if (lane == 0) { wneg[0 * 8 + w] = neg0; wneg[1 * 8 + w] = neg1; }
    __syncthreads();
    if (tid < 2) {
        float s = 0.f;
        for (int i = 0; i < 8; i++) s += wneg[tid * 8 + i];
        atomicAdd(&g_rowsum2[b0 + tid], s);
    }
}

// ---------------------------------------------------------------------------
// K3: HMMA GEMM — EXACT R11 core (KC=32, 3-stage cp.async, contiguous warp
// loads, in-place B convert). Only epilogue diff: s_invn -> s_ivk (= KE*invn)
// and fexp2 polynomial -> single MUFU ex2.approx. No new live registers.
__global__ void __launch_bounds__(256, 2)
k_gemm(const float* __restrict__ Wt, const float* __restrict__ Qu, const int* __restrict__ label) {
    extern __shared__ uint8_t sm[];
    __shared__ float s_nsq[BN];
    __shared__ float s_ivk[BN];
    __shared__ float s_row[BM];
    __shared__ int s_lab[BM];

    if (blockIdx.y >= NTILES) {
        int cidx = (int)blockIdx.x + 2 * ((int)blockIdx.y - NTILES);  // 0..127
        do_correct(cidx * 2, (int)blockIdx.z * 128, label, sm);
        return;
    }

    int pass = blockIdx.z;
    const float* W = pass ? Qu : Wt;
    int m0 = blockIdx.x * BM;
    int c0 = blockIdx.y * BN;
    int tid = threadIdx.x;
    int wid = tid >> 5, lane = tid & 31;
    int mw = wid >> 2, nw = wid & 3;     // 2x4 warp grid, 64x32 warp tile
    int rin = lane & 7, seg = lane >> 3;

    if (tid < BM) { s_row[tid] = 0.f; s_lab[tid] = label[m0 + tid]; }

    // --- contiguous warp-level load mapping ---
    int arow0 = 16 * wid + (lane >> 2);        // A: 8 rows x 4 lanes per instr
    int aq    = lane & 3;
    int brow0 = 16 * wid + (lane >> 3);        // B: 4 rows x 8 lanes per instr
    int bq    = lane & 7;
    const uint8_t* aAg = (const uint8_t*)(g_embh + (size_t)(m0 + arow0) * FF) + aq * 16;
    const uint8_t* bAg[4];
#pragma unroll
    for (int i = 0; i < 4; i++) {
        int gr = min(c0 + brow0 + 4 * i, CC - 1);
        bAg[i] = (const uint8_t*)(W + (size_t)gr * FF) + bq * 16;
    }

    uint32_t aAs = s2u(sm + OFF_AS);
    uint32_t aBst = s2u(sm + OFF_B);
    uint32_t aoff0 = (uint32_t)(arow0 * 80 + aq * 16);
    uint32_t boffL[4];
#pragma unroll
    for (int i = 0; i < 4; i++) boffL[i] = (uint32_t)((brow0 + 4 * i) * 144 + bq * 16);

    // convert mapping: thread handles row crow, 64B half ch (its own warp's cp data)
    int crow = tid >> 1, ch = tid & 1;
    uint32_t cvoff = (uint32_t)(crow * 144 + ch * 64);

    float d[4][4][4];
#pragma unroll
    for (int i = 0; i < 4; i++)
#pragma unroll
        for (int j = 0; j < 4; j++)
#pragma unroll
            for (int e = 0; e < 4; e++) d[i][j][e] = 0.f;
    float ssacc = 0.f;

#define ISSUE(k) do { \
        int _s = (k) % 3; \
        uint32_t ad = aAs + _s * ASB + aoff0; \
        const uint8_t* ag = aAg + (size_t)(k) * 64; \
        cp16(ad, ag); \
        cp16(ad + 8 * 80, ag + (size_t)8 * FF * 2); \
        uint32_t bd = aBst + _s * BSTB; \
        cp16(bd + boffL[0], bAg[0] + (size_t)(k) * 128); \
        cp16(bd + boffL[1], bAg[1] + (size_t)(k) * 128); \
        cp16(bd + boffL[2], bAg[2] + (size_t)(k) * 128); \
        cp16(bd + boffL[3], bAg[3] + (size_t)(k) * 128); \
        CP_COMMIT(); \
    } while (0)

    // in-place fp32 -> bf16 (sparse groups): reads its own warp's 64B, writes subsets
#define CONVERT(k) do { \
        uint8_t* bp = sm + OFF_B + ((k) % 3) * BSTB + cvoff; \
        float4 f0 = *(float4*)(bp);      float4 f1 = *(float4*)(bp + 16); \
        float4 f2 = *(float4*)(bp + 32); float4 f3 = *(float4*)(bp + 48); \
        ssacc += f0.x * f0.x + f0.y * f0.y + f0.z * f0.z + f0.w * f0.w \
               + f1.x * f1.x + f1.y * f1.y + f1.z * f1.z + f1.w * f1.w \
               + f2.x * f2.x + f2.y * f2.y + f2.z * f2.z + f2.w * f2.w \
               + f3.x * f3.x + f3.y * f3.y + f3.z * f3.z + f3.w * f3.w; \
        uint4 q0, q1; \
        q0.x = pk(f0.x, f0.y); q0.y = pk(f0.z, f0.w); \
        q0.z = pk(f1.x, f1.y); q0.w = pk(f1.z, f1.w); \
        q1.x = pk(f2.x, f2.y); q1.y = pk(f2.z, f2.w); \
        q1.z = pk(f3.x, f3.y); q1.w = pk(f3.z, f3.w); \
        *(uint4*)(bp) = q0; \
        *(uint4*)(bp + 32) = q1; \
    } while (0)

    ISSUE(0);
    ISSUE(1);
    CP_WAIT1();
    __syncwarp();
    CONVERT(0);

    for (int c = 0; c < NCH; c++) {
        __syncthreads();
        if (c + 2 < NCH) ISSUE(c + 2);
        // ---- MMA on chunk c first (bf16 already in place)
        uint32_t bas = aAs + (c % 3) * ASB;
        uint32_t bbs = aBst + (c % 3) * BSTB;
#pragma unroll
        for (int ks = 0; ks < 2; ks++) {
            int kk = ks * 16;
            uint32_t bfr[4][2];
#pragma unroll
            for (int bh = 0; bh < 2; bh++) {
                int row = nw * 32 + bh * 16 + (seg >> 1) * 8 + rin;
                uint32_t r0, r1, r2, r3;
                LDSM4(r0, r1, r2, r3, bbs + (uint32_t)(row * 144 + kk * 4 + (seg & 1) * 32));
                bfr[bh * 2][0] = r0;     bfr[bh * 2][1] = r1;
                bfr[bh * 2 + 1][0] = r2; bfr[bh * 2 + 1][1] = r3;
            }
#pragma unroll
            for (int mf = 0; mf < 4; mf++) {
                int row = mw * 64 + mf * 16 + (seg & 1) * 8 + rin;
                int col = kk + (seg >> 1) * 8;
                uint32_t af[4];
                LDSM4(af[0], af[1], af[2], af[3], bas + (uint32_t)(row * STRA + col) * 2);
#pragma unroll
                for (int nt = 0; nt < 4; nt++) MMA16816(d[mf][nt], af, bfr[nt]);
            }
        }
        // ---- then wait for chunk c+1 and convert in place
        if (c + 1 < NCH) {
            if (c + 2 < NCH) CP_WAIT1(); else CP_WAIT0();
            __syncwarp();
            CONVERT(c + 1);
        }
    }

    // class norms: threads (2r, 2r+1) covered row r
    ssacc += __shfl_xor_sync(0xffffffffu, ssacc, 1);
    if (ch == 0) s_nsq[crow] = ssacc;
    __syncthreads();
    if (tid < BN) s_ivk[tid] = KE / fmaxf(sqrtf(s_nsq[tid]), pass ? 1e-12f : 1e-5f);
    __syncthreads();

    // epilogue — R11 structure; exp via one MUFU ex2.approx per element
    int g4 = lane >> 2, j4 = lane & 3;
#pragma unroll
    for (int mf = 0; mf < 4; mf++) {
        int ra = mw * 64 + mf * 16 + g4;
        int rb = ra + 8;
        int la = s_lab[ra], lb = s_lab[rb];
        float sa = 0.f, sb = 0.f;
#pragma unroll
        for (int nt = 0; nt < 4; nt++) {
            int cbase = nw * 32 + nt * 8 + j4 * 2;
#pragma unroll
            for (int e = 0; e < 2; e++) {
                int lc = cbase + e;
                int gc = c0 + lc;
                if (gc < CC) {
                    float ivk = s_ivk[lc];
                    if (pass == 0 && gc == la)
                        g_pos1[m0 + ra] = ex2(fmaf(-d[mf][nt][e], ivk, KEM));
                    else sa += ex2(d[mf][nt][e] * ivk);
                    if (pass == 0 && gc == lb)
                        g_pos1[m0 + rb] = ex2(fmaf(-d[mf][nt][e + 2], ivk, KEM));
                    else sb += ex2(d[mf][nt][e + 2] * ivk);
                }
            }
        }
        sa += __shfl_xor_sync(0xffffffffu, sa, 1);
        sa += __shfl_xor_sync(0xffffffffu, sa, 2);
        sb += __shfl_xor_sync(0xffffffffu, sb, 1);
        sb += __shfl_xor_sync(0xffffffffu, sb, 2);
        if (j4 == 0) { atomicAdd(&s_row[ra], sa); atomicAdd(&s_row[rb], sb); }
    }
    __syncthreads();
    if (tid < BM)
        atomicAdd(pass ? &g_rowsum2[m0 + tid] : &g_rowsum1[m0 + tid], s_row[tid]);
#undef ISSUE
#undef CONVERT
}

// ---------------------------------------------------------------------------
// K6: EPL loss
__global__ void k_final(float* __restrict__ out) {
    int t = threadIdx.x;
    __shared__ float red[256];
    float v = log1pf(g_rowsum1[t] * g_pos1[t]) + log1pf(g_rowsum2[t] * g_pos2[t]);
    red[t] = v; __syncthreads();
    for (int o = 128; o > 0; o >>= 1) { if (t < o) red[t] += red[t + o]; __syncthreads(); }
    if (t == 0) out[0] = red[0] / (2.f * BB);
}

// ---------------------------------------------------------------------------
extern "C" void kernel_launch(void* const* d_in, const int* in_sizes, int n_in,
                              void* d_out, int out_size) {
    const float* inp    = (const float*)d_in[0];
    const float* weight = (const float*)d_in[1];
    const float* queue  = (const float*)d_in[2];
    const int*   label  = (const int*)d_in[3];
    float* out = (float*)d_out;

    cudaFuncSetAttribute(k_gemm, cudaFuncAttributeMaxDynamicSharedMemorySize, DSMEM);

    k_norm_input<<<BB, 128>>>(inp);
    k_queue_update<<<BB, 128>>>(queue, label);
    k_nop<<<1, 32>>>();                   // spacer: puts k_gemm in the ncu slot
    dim3 grid(2, NTILES + CEX, 2);
    k_gemm<<<grid, 256, DSMEM>>>(weight, queue, label);
    k_final<<<1, 256>>>(out);
}

// round 15
// speedup vs baseline: 1.6802x; 1.0056x over previous
#include <cuda_runtime.h>
#include <cuda_bf16.h>
#include <cstdint>
#include <math.h>

#define BB 256
#define FF 512
#define CC 100000
#define SSC 64.0f
#define MMAR 0.4f
#define KVP 0.7f

#define BM 256                        // full batch per CTA: B loaded+converted ONCE
#define BN 64
#define KC 32
#define NCH (FF / KC)                 // 16
#define NT2 ((CC + BN - 1) / BN)      // 1563
#define CEX 128                       // overflow x-blocks carrying k_correct work

// A: 80B-stride rows (64B chunk data + pad) — 20r mod 32 distinct for r 0..7
// B staging: 144B-stride rows; fp32 in place, bf16 groups sparse (as R14)
#define ASB 20480                     // 256*80
#define BSTB 9216                     // 64*144
#define OFF_AS 0
#define OFF_B (3 * ASB)               // 61440
#define DSMEM (OFF_B + 3 * BSTB)      // 89088

#define KE  92.33248261972343f        // SSC * log2(e)
#define KEM 36.93299304788937f        // KE * MMAR

__device__ float g_emb[BB * FF];
__device__ __nv_bfloat16 g_embh[BB * FF];
__device__ float g_newq[BB * FF];
__device__ float g_oldn[BB * FF];
__device__ float g_rowsum1[BB];
__device__ float g_rowsum2[BB];
__device__ float g_pos1[BB];
__device__ float g_pos2[BB];
__device__ int   g_owner[BB];

static __device__ __forceinline__ uint32_t s2u(const void* p) {
    uint32_t a;
    asm("{ .reg .u64 t; cvta.to.shared.u64 t, %1; cvt.u32.u64 %0, t; }" : "=r"(a) : "l"(p));
    return a;
}

static __device__ __forceinline__ float ex2(float x) {
    float r;
    asm("ex2.approx.f32 %0, %1;" : "=f"(r) : "f"(x));
    return r;
}

#define LDSM4(r0, r1, r2, r3, addr) \
    asm volatile("ldmatrix.sync.aligned.m8n8.x4.shared.b16 {%0,%1,%2,%3}, [%4];" \
                 : "=r"(r0), "=r"(r1), "=r"(r2), "=r"(r3) : "r"(addr))

#define MMA16816(d, a, b) \
    asm volatile("mma.sync.aligned.m16n8k16.row.col.f32.bf16.bf16.f32 " \
                 "{%0,%1,%2,%3},{%4,%5,%6,%7},{%8,%9},{%0,%1,%2,%3};" \
                 : "+f"((d)[0]), "+f"((d)[1]), "+f"((d)[2]), "+f"((d)[3]) \
                 : "r"((a)[0]), "r"((a)[1]), "r"((a)[2]), "r"((a)[3]), \
                   "r"((b)[0]), "r"((b)[1]))

static __device__ __forceinline__ void cp16(uint32_t dst, const void* gsrc) {
    asm volatile("cp.async.cg.shared.global [%0], [%1], 16;"
                 :: "r"(dst), "l"(gsrc) : "memory");
}
#define CP_COMMIT() asm volatile("cp.async.commit_group;" ::: "memory")
#define CP_WAIT0()  asm volatile("cp.async.wait_group 0;" ::: "memory")
#define CP_WAIT1()  asm volatile("cp.async.wait_group 1;" ::: "memory")

static __device__ __forceinline__ uint32_t pk(float x, float y) {
    __nv_bfloat162 h = __floats2bfloat162_rn(x, y);
    return *(uint32_t*)&h;
}

// ---------------------------------------------------------------------------
// K1: normalize input rows (eps 1e-5)
__global__ void k_norm_input(const float* __restrict__ inp) {
    int b = blockIdx.x, t = threadIdx.x;
    __shared__ float red[128];
    float s = 0.f;
    for (int k = t; k < FF; k += 128) { float v = inp[b * FF + k]; s += v * v; }
    red[t] = s; __syncthreads();
    for (int o = 64; o > 0; o >>= 1) { if (t < o) red[t] += red[t + o]; __syncthreads(); }
    float inv = 1.f / fmaxf(sqrtf(red[0]), 1e-5f);
    for (int k = t; k < FF; k += 128) {
        float e = inp[b * FF + k] * inv;
        g_emb[b * FF + k] = e;
        g_embh[b * FF + k] = __float2bfloat16(e);
    }
    if (t == 0) { g_rowsum1[b] = 0.f; g_rowsum2[b] = 0.f; }
}

// ---------------------------------------------------------------------------
// K2: virtual-prototype update for the 256 labeled rows (queue untouched)
__global__ void k_queue_update(const float* __restrict__ queue, const int* __restrict__ label) {
    int b = blockIdx.x, t = threadIdx.x;
    int lb = label[b];
    const float* q = queue + (size_t)lb * FF;
    const float* e = g_emb + b * FF;
    __shared__ float r1[128], r2[128];
    float sq = 0.f, dd = 0.f;
    for (int k = t; k < FF; k += 128) { float qa = q[k], ea = e[k]; sq += qa * qa; dd += qa * ea; }
    r1[t] = sq; r2[t] = dd; __syncthreads();
    for (int o = 64; o > 0; o >>= 1) {
        if (t < o) { r1[t] += r1[t + o]; r2[t] += r2[t + o]; }
        __syncthreads();
    }
    float invold = 1.f / fmaxf(sqrtf(r1[0]), 1e-12f);
    float drift = r2[0];
    float factor = drift / (1.f + fabsf(drift));
    __syncthreads();
    float sn = 0.f;
    for (int k = t; k < FF; k += 128) {
        float v = factor * q[k] + (1.f - factor) * e[k];
        sn += v * v;
    }
    r1[t] = sn; __syncthreads();
    for (int o = 64; o > 0; o >>= 1) { if (t < o) r1[t] += r1[t + o]; __syncthreads(); }
    float invnew = 1.f / fmaxf(sqrtf(r1[0]), 1e-12f);
    for (int k = t; k < FF; k += 128) {
        float v = factor * q[k] + (1.f - factor) * e[k];
        g_newq[b * FF + k] = v * invnew;
        g_oldn[b * FF + k] = q[k] * invold;
    }
    if (t == 0) {
        int own = 1;
        for (int j = b + 1; j < BB; j++) if (label[j] == lb) { own = 0; break; }
        g_owner[b] = own;
    }
}

// ---------------------------------------------------------------------------
// no-op spacer so k_gemm lands in the ncu capture slot (launch #4)
__global__ void k_nop() {}

// ---------------------------------------------------------------------------
// queue-column fixups, executed by overflow blocks of the GEMM grid.
static __device__ void do_correct(int b0, int jbase, const int* __restrict__ label,
                                  uint8_t* sm) {
    float4* es0 = (float4*)sm;
    float4* es1 = es0 + FF / 4;
    float*  wneg = (float*)(es1 + FF / 4);
    int tid = threadIdx.x;
    int w = tid >> 5, lane = tid & 31;
    for (int k = tid; k < FF / 4; k += 256) {
        es0[k] = ((const float4*)(g_emb + (size_t)b0 * FF))[k];
        es1[k] = ((const float4*)(g_emb + (size_t)(b0 + 1) * FF))[k];
    }
    __syncthreads();
    int lab0 = label[b0], lab1 = label[b0 + 1];
    float neg0 = 0.f, neg1 = 0.f;
#pragma unroll 1
    for (int it = 0; it < 4; it++) {
        int j0 = jbase + (w + 8 * it) * 4;
        float doo[2][4] = {}, dnn[2][4] = {};
#pragma unroll
        for (int kit = 0; kit < 4; kit++) {
            int k4 = lane + 32 * kit;
            float4 e0 = es0[k4], e1 = es1[k4];
#pragma unroll
            for (int s = 0; s < 4; s++) {
                float4 o4 = ((const float4*)(g_oldn + (size_t)(j0 + s) * FF))[k4];
                float4 n4 = ((const float4*)(g_newq + (size_t)(j0 + s) * FF))[k4];
                doo[0][s] += e0.x * o4.x + e0.y * o4.y + e0.z * o4.z + e0.w * o4.w;
                dnn[0][s] += e0.x * n4.x + e0.y * n4.y + e0.z * n4.z + e0.w * n4.w;
                doo[1][s] += e1.x * o4.x + e1.y * o4.y + e1.z * o4.z + e1.w * o4.w;
                dnn[1][s] += e1.x * n4.x + e1.y * n4.y + e1.z * n4.z + e1.w * n4.w;
            }
        }
#pragma unroll
        for (int o = 16; o > 0; o >>= 1)
#pragma unroll
            for (int s = 0; s < 4; s++) {
                doo[0][s] += __shfl_xor_sync(0xffffffffu, doo[0][s], o);
                dnn[0][s] += __shfl_xor_sync(0xffffffffu, dnn[0][s], o);
                doo[1][s] += __shfl_xor_sync(0xffffffffu, doo[1][s], o);
                dnn[1][s] += __shfl_xor_sync(0xffffffffu, dnn[1][s], o);
            }
        if (lane < 4) {
            int j = j0 + lane;
            if (g_owner[j]) {
                int lj = label[j];
                neg0 -= __expf(SSC * doo[0][lane]);
                if (lj == lab0) g_pos2[b0] = __expf(-SSC * (1.f - KVP) * dnn[0][lane]);
                else neg0 += __expf(SSC * dnn[0][lane]);
                neg1 -= __expf(SSC * doo[1][lane]);
                if (lj == lab1) g_pos2[b0 + 1] = __expf(-SSC * (1.f - KVP) * dnn[1][lane]);
                else neg1 += __expf(SSC * dnn[1][lane]);
            }
        }
    }
    neg0 += __shfl_xor_sync(0xffffffffu, neg0, 1);
    neg0 += __shfl_xor_sync(0xffffffffu, neg0, 2);
    neg1 += __shfl_xor_sync(0xffffffffu, neg1, 1);
    neg1 += __shfl_xor_sync(0xffffffffu, neg1, 2);
    if (lane == 0) { wneg[0 * 8 + w] = neg0; wneg[1 * 8 + w] = neg1; }
    __syncthreads();
    if (tid < 2) {
        float s = 0.f;
        for (int i = 0; i < 8; i++) s += wneg[tid * 8 + i];
        atomicAdd(&g_rowsum2[b0 + tid], s);
    }
}

// ---------------------------------------------------------------------------
// K3: HMMA GEMM, BM=256 x BN=64 (B loaded+converted once per class tile).
// KC=32, 3-stage cp.async, contiguous warp loads, in-place B convert,
// MUFU ex2 epilogue.  grid(NT2+CEX, 2): x = class tile, y = pass.
__global__ void __launch_bounds__(256, 2)
k_gemm(const float* __restrict__ Wt, const float* __restrict__ Qu, const int* __restrict__ label) {
    extern __shared__ uint8_t sm[];
    __shared__ float s_nsq[BN];
    __shared__ float s_ivk[BN];
    __shared__ float s_row[BM];
    __shared__ int s_lab[BM];

    if (blockIdx.x >= NT2) {
        int cidx = (int)blockIdx.x - NT2;                  // 0..127
        do_correct(cidx * 2, (int)blockIdx.y * 128, label, sm);
        return;
    }

    int pass = blockIdx.y;
    const float* W = pass ? Qu : Wt;
    int c0 = blockIdx.x * BN;
    int tid = threadIdx.x;
    int wid = tid >> 5, lane = tid & 31;
    int mw = wid >> 1, nw = wid & 1;     // 4x2 warp grid, 64x32 warp tile
    int rin = lane & 7, seg = lane >> 3;

    s_row[tid] = 0.f; s_lab[tid] = label[tid];

    // --- contiguous warp-level load mappings ---
    // A: 4 instrs/thread; instr i covers rows 32w+8i..+7 (4 lanes x 16B per row)
    int arow0 = 32 * wid + (lane >> 2);
    int aq    = lane & 3;
    const uint8_t* aAg = (const uint8_t*)(g_embh + (size_t)arow0 * FF) + aq * 16;
    uint32_t aoff0 = (uint32_t)(arow0 * 80 + aq * 16);
    // B: 2 instrs/thread; instr i covers rows 8w+4i..+3 (8 lanes x 16B per row)
    int brow0 = 8 * wid + (lane >> 3);
    int bq    = lane & 7;
    const uint8_t* bAg[2];
#pragma unroll
    for (int i = 0; i < 2; i++) {
        int gr = min(c0 + brow0 + 4 * i, CC - 1);
        bAg[i] = (const uint8_t*)(W + (size_t)gr * FF) + bq * 16;
    }
    uint32_t boffL[2];
#pragma unroll
    for (int i = 0; i < 2; i++) boffL[i] = (uint32_t)((brow0 + 4 * i) * 144 + bq * 16);

    uint32_t aAs = s2u(sm + OFF_AS);
    uint32_t aBst = s2u(sm + OFF_B);

    // convert mapping: thread owns 32B group cg of row crow (own warp's cp data)
    int crow = 8 * wid + (lane >> 2), cg = lane & 3;
    uint32_t cvoff = (uint32_t)(crow * 144 + cg * 32);

    float d[4][4][4];
#pragma unroll
    for (int i = 0; i < 4; i++)
#pragma unroll
        for (int j = 0; j < 4; j++)
#pragma unroll
            for (int e = 0; e < 4; e++) d[i][j][e] = 0.f;
    float ssacc = 0.f;

#define ISSUE(k) do { \
        int _s = (k) % 3; \
        uint32_t ad = aAs + _s * ASB + aoff0; \
        const uint8_t* ag = aAg + (size_t)(k) * 64; \
        cp16(ad,        ag); \
        cp16(ad + 640,  ag + 8192); \
        cp16(ad + 1280, ag + 16384); \
        cp16(ad + 1920, ag + 24576); \
        uint32_t bd = aBst + _s * BSTB; \
        cp16(bd + boffL[0], bAg[0] + (size_t)(k) * 128); \
        cp16(bd + boffL[1], bAg[1] + (size_t)(k) * 128); \
        CP_COMMIT(); \
    } while (0)

    // in-place fp32 -> bf16 (sparse groups): own 32B -> 16B at group start
#define CONVERT(k) do { \
        uint8_t* bp = sm + OFF_B + ((k) % 3) * BSTB + cvoff; \
        float4 f0 = *(float4*)(bp); \
        float4 f1 = *(float4*)(bp + 16); \
        ssacc += f0.x * f0.x + f0.y * f0.y + f0.z * f0.z + f0.w * f0.w \
               + f1.x * f1.x + f1.y * f1.y + f1.z * f1.z + f1.w * f1.w; \
        uint4 q0; \
        q0.x = pk(f0.x, f0.y); q0.y = pk(f0.z, f0.w); \
        q0.z = pk(f1.x, f1.y); q0.w = pk(f1.z, f1.w); \
        *(uint4*)(bp) = q0; \
    } while (0)

    ISSUE(0);
    ISSUE(1);
    CP_WAIT1();
    __syncwarp();
    CONVERT(0);

    for (int c = 0; c < NCH; c++) {
        __syncthreads();
        if (c + 2 < NCH) ISSUE(c + 2);
        // ---- MMA on chunk c first (bf16 already in place)
        uint32_t bas = aAs + (c % 3) * ASB;
        uint32_t bbs = aBst + (c % 3) * BSTB;
#pragma unroll
        for (int ks = 0; ks < 2; ks++) {
            int kk = ks * 16;
            uint32_t bfr[4][2];
#pragma unroll
            for (int bh = 0; bh < 2; bh++) {
                int row = nw * 32 + bh * 16 + (seg >> 1) * 8 + rin;
                uint32_t r0, r1, r2, r3;
                LDSM4(r0, r1, r2, r3, bbs + (uint32_t)(row * 144 + kk * 4 + (seg & 1) * 32));
                bfr[bh * 2][0] = r0;     bfr[bh * 2][1] = r1;
                bfr[bh * 2 + 1][0] = r2; bfr[bh * 2 + 1][1] = r3;
            }
#pragma unroll
            for (int mf = 0; mf < 4; mf++) {
                int row = mw * 64 + mf * 16 + (seg & 1) * 8 + rin;
                int col = kk + (seg >> 1) * 8;
                uint32_t af[4];
                LDSM4(af[0], af[1], af[2], af[3], bas + (uint32_t)(row * 80 + col * 2));
#pragma unroll
                for (int nt = 0; nt < 4; nt++) MMA16816(d[mf][nt], af, bfr[nt]);
            }
        }
        // ---- then wait for chunk c+1 and convert in place
        if (c + 1 < NCH) {
            if (c + 2 < NCH) CP_WAIT1(); else CP_WAIT0();
            __syncwarp();
            CONVERT(c + 1);
        }
    }

    // class norms: 4 lanes (cg 0..3) covered row crow
    ssacc += __shfl_xor_sync(0xffffffffu, ssacc, 1);
    ssacc += __shfl_xor_sync(0xffffffffu, ssacc, 2);
    if (cg == 0) s_nsq[crow] = ssacc;
    __syncthreads();
    if (tid < BN) s_ivk[tid] = KE / fmaxf(sqrtf(s_nsq[tid]), pass ? 1e-12f : 1e-5f);
    __syncthreads();

    // epilogue — MUFU ex2 per element
    int g4 = lane >> 2, j4 = lane & 3;
#pragma unroll
    for (int mf = 0; mf < 4; mf++) {
        int ra = mw * 64 + mf * 16 + g4;
        int rb = ra + 8;
        int la = s_lab[ra], lb = s_lab[rb];
        float sa = 0.f, sb = 0.f;
#pragma unroll
        for (int nt = 0; nt < 4; nt++) {
            int cbase = nw * 32 + nt * 8 + j4 * 2;
#pragma unroll
            for (int e = 0; e < 2; e++) {
                int lc = cbase + e;
                int gc = c0 + lc;
                if (gc < CC) {
                    float ivk = s_ivk[lc];
                    if (pass == 0 && gc == la)
                        g_pos1[ra] = ex2(fmaf(-d[mf][nt][e], ivk, KEM));
                    else sa += ex2(d[mf][nt][e] * ivk);
                    if (pass == 0 && gc == lb)
                        g_pos1[rb] = ex2(fmaf(-d[mf][nt][e + 2], ivk, KEM));
                    else sb += ex2(d[mf][nt][e + 2] * ivk);
                }
            }
        }
        sa += __shfl_xor_sync(0xffffffffu, sa, 1);
        sa += __shfl_xor_sync(0xffffffffu, sa, 2);
        sb += __shfl_xor_sync(0xffffffffu, sb, 1);
        sb += __shfl_xor_sync(0xffffffffu, sb, 2);
        if (j4 == 0) { atomicAdd(&s_row[ra], sa); atomicAdd(&s_row[rb], sb); }
    }
    __syncthreads();
    atomicAdd(pass ? &g_rowsum2[tid] : &g_rowsum1[tid], s_row[tid]);
#undef ISSUE
#undef CONVERT
}

// ---------------------------------------------------------------------------
// K6: EPL loss
__global__ void k_final(float* __restrict__ out) {
    int t = threadIdx.x;
    __shared__ float red[256];
    float v = log1pf(g_rowsum1[t] * g_pos1[t]) + log1pf(g_rowsum2[t] * g_pos2[t]);
    red[t] = v; __syncthreads();
    for (int o = 128; o > 0; o >>= 1) { if (t < o) red[t] += red[t + o]; __syncthreads(); }
    if (t == 0) out[0] = red[0] / (2.f * BB);
}

// ---------------------------------------------------------------------------
extern "C" void kernel_launch(void* const* d_in, const int* in_sizes, int n_in,
                              void* d_out, int out_size) {
    const float* inp    = (const float*)d_in[0];
    const float* weight = (const float*)d_in[1];
    const float* queue  = (const float*)d_in[2];
    const int*   label  = (const int*)d_in[3];
    float* out = (float*)d_out;

    cudaFuncSetAttribute(k_gemm, cudaFuncAttributeMaxDynamicSharedMemorySize, DSMEM);

    k_norm_input<<<BB, 128>>>(inp);
    k_queue_update<<<BB, 128>>>(queue, label);
    k_nop<<<1, 32>>>();                   // spacer: puts k_gemm in the ncu slot
    dim3 grid(NT2 + CEX, 2);
    k_gemm<<<grid, 256, DSMEM>>>(weight, queue, label);
    k_final<<<1, 256>>>(out);
}